// round 5
// baseline (speedup 1.0000x reference)
#include <cuda_runtime.h>

// Problem shape (fixed by the dataset)
#define W_  1920
#define H_  1080
#define B_  4
#define C_  3
constexpr int HW = H_ * W_;     // 2,073,600
constexpr int N  = B_ * HW;     // 8,294,400

// Scratch (cudaMalloc forbidden -> static device globals, zero-initialized at load).
// INVARIANT: g_dbuf and g_acc are all-zero at entry of every kernel_launch call.
// Both are re-zeroed by k_norm at the end of each call; the first call uses the
// loader's zeros.
__device__ int                  g_dbuf[N];   // quantized motion-magnitude depth buffer
__device__ __align__(16) float4 g_acc[N];    // AoS: {weight, c0, c1, c2} per pixel

// One 16-byte vector reduction instead of 4 scalar float atomics.
__device__ __forceinline__ void red_add_v4(float4* p, float a, float b, float c, float d)
{
    asm volatile("red.global.add.v4.f32 [%0], {%1, %2, %3, %4};"
                 :: "l"(p), "f"(a), "f"(b), "f"(c), "f"(d) : "memory");
}

__device__ __forceinline__ int depth_key(float fx, float fy)
{
    // round-half-even (matches jnp.round), IEEE sqrt regardless of fast-math
    return __float2int_rn(__fsqrt_rn(fx * fx + fy * fy) * 1000.0f);
}

// ---------------------------------------------------------------------------
// Pass 1: scatter-max depth buffer. PURE pass: one flow read + up to 4 RED.MAX,
// nothing else -- keeps the 33MB dbuf L2-resident with no store pollution.
// All in-bounds corners participate regardless of bilinear weight (a zero-weight
// corner can still suppress other pixels' contributions).
// ---------------------------------------------------------------------------
__global__ void __launch_bounds__(256) k_depth(const float2* __restrict__ flow)
{
    int i = blockIdx.x * blockDim.x + threadIdx.x;
    if (i >= N) return;

    int b = i / HW;
    int p = i - b * HW;
    int h = p / W_;
    int w = p - h * W_;

    float2 f = flow[i];
    int x0 = (int)floorf((float)w + f.x);
    int y0 = (int)floorf((float)h + f.y);
    int d  = depth_key(f.x, f.y);

    int* bufb = g_dbuf + b * HW;
    bool vx0 = (x0 >= 0)     & (x0 < W_);
    bool vx1 = (x0 + 1 >= 0) & (x0 + 1 < W_);
    if (y0 >= 0 && y0 < H_) {
        int* row = bufb + y0 * W_;
        if (vx0) atomicMax(row + x0, d);
        if (vx1) atomicMax(row + x0 + 1, d);
    }
    if (y0 + 1 >= 0 && y0 + 1 < H_) {
        int* row = bufb + (y0 + 1) * W_;
        if (vx0) atomicMax(row + x0, d);
        if (vx1) atomicMax(row + x0 + 1, d);
    }
}

// ---------------------------------------------------------------------------
// Pass 2: accumulate depth-test winners, ONE vec4 reduction per winning corner.
// ---------------------------------------------------------------------------
__global__ void __launch_bounds__(256) k_accum(const float* __restrict__ im0,
                                               const float2* __restrict__ flow)
{
    int i = blockIdx.x * blockDim.x + threadIdx.x;
    if (i >= N) return;

    int b = i / HW;
    int p = i - b * HW;
    int h = p / W_;
    int w = p - h * W_;

    float2 f = flow[i];
    float x = (float)w + f.x;
    float y = (float)h + f.y;
    float x0f = floorf(x);
    float y0f = floorf(y);
    float ax = x - x0f;
    float ay = y - y0f;
    int x0 = (int)x0f;
    int y0 = (int)y0f;
    int d  = depth_key(f.x, f.y);

    // source pixel values (3 channels, planar)
    const float* src = im0 + (size_t)b * 3 * HW + p;
    float v0 = __ldg(src);
    float v1 = __ldg(src + HW);
    float v2 = __ldg(src + 2 * HW);

    float wx1 = ax, wx0 = 1.0f - ax;
    float wy1 = ay, wy0 = 1.0f - ay;
    float wts[4] = { wx0 * wy0, wx1 * wy0, wx0 * wy1, wx1 * wy1 };
    int   txs[4] = { x0, x0 + 1, x0,     x0 + 1 };
    int   tys[4] = { y0, y0,     y0 + 1, y0 + 1 };

    int base = b * HW;
#pragma unroll
    for (int k = 0; k < 4; k++) {
        int tx = txs[k];
        int ty = tys[k];
        if (tx < 0 || tx >= W_ || ty < 0 || ty >= H_) continue;
        int idx = base + ty * W_ + tx;
        if (__ldg(&g_dbuf[idx]) != d) continue;   // depth test (d >= 0 always)
        float wv = wts[k];
        if (wv == 0.0f) continue;                 // adding exact 0.0 is an identity
        red_add_v4(&g_acc[idx], wv, wv * v0, wv * v1, wv * v2);
    }
}

// ---------------------------------------------------------------------------
// Pass 3: normalize (4 pixels/thread) + re-zero g_acc (lines are L2-hot from
// the loads just above) and g_dbuf for the next call.
// out[b][c][h][w] = acc.c / max(acc.w, eps)
// ---------------------------------------------------------------------------
__global__ void __launch_bounds__(256) k_norm(float* __restrict__ out)
{
    int t = blockIdx.x * blockDim.x + threadIdx.x;
    if (t >= N / 4) return;

    int i = t * 4;            // first pixel of this group (HW % 4 == 0 -> same b)
    int b = i / HW;
    int p = i - b * HW;

    float4 a0 = g_acc[i];
    float4 a1 = g_acc[i + 1];
    float4 a2 = g_acc[i + 2];
    float4 a3 = g_acc[i + 3];

    // re-zero scratch for the next kernel_launch call (deterministic: loader
    // zeros on first call, these stores on all subsequent calls)
    const float4 z = make_float4(0.f, 0.f, 0.f, 0.f);
    g_acc[i]     = z;
    g_acc[i + 1] = z;
    g_acc[i + 2] = z;
    g_acc[i + 3] = z;
    reinterpret_cast<int4*>(g_dbuf)[t] = make_int4(0, 0, 0, 0);

    float r0 = 1.0f / fmaxf(a0.x, 1e-5f);
    float r1 = 1.0f / fmaxf(a1.x, 1e-5f);
    float r2 = 1.0f / fmaxf(a2.x, 1e-5f);
    float r3 = 1.0f / fmaxf(a3.x, 1e-5f);

    float* dst = out + (size_t)b * 3 * HW + p;    // p % 4 == 0 -> 16B aligned
    reinterpret_cast<float4*>(dst)[0]          = make_float4(a0.y * r0, a1.y * r1, a2.y * r2, a3.y * r3);
    reinterpret_cast<float4*>(dst + HW)[0]     = make_float4(a0.z * r0, a1.z * r1, a2.z * r2, a3.z * r3);
    reinterpret_cast<float4*>(dst + 2 * HW)[0] = make_float4(a0.w * r0, a1.w * r1, a2.w * r2, a3.w * r3);
}

// ---------------------------------------------------------------------------
extern "C" void kernel_launch(void* const* d_in, const int* in_sizes, int n_in,
                              void* d_out, int out_size)
{
    const float*  im0  = (const float*)d_in[0];   // [B,C,H,W] float32
    const float2* flow = (const float2*)d_in[1];  // [B,H,W,2] float32
    float*        out  = (float*)d_out;           // [B,C,H,W] float32

    const int T = 256;
    k_depth<<<(N + T - 1) / T, T>>>(flow);
    k_accum<<<(N + T - 1) / T, T>>>(im0, flow);
    k_norm <<<(N / 4 + T - 1) / T, T>>>(out);

    (void)in_sizes; (void)n_in; (void)out_size;
}

// round 6
// speedup vs baseline: 1.3207x; 1.3207x over previous
#include <cuda_runtime.h>

// Problem shape (fixed by the dataset)
#define W_  1920
#define H_  1080
#define B_  4
#define C_  3
constexpr int HW = H_ * W_;     // 2,073,600
constexpr int N  = B_ * HW;     // 8,294,400

// Scratch (cudaMalloc forbidden -> static device globals, zero-initialized at load).
// INVARIANT at entry of every kernel_launch: g_dbuf all-zero (re-zeroed by k_norm
// tail each call), g_acc all-zero-or-overwritten (re-zeroed by k_depth each call).
__device__ __align__(16) int    g_dbuf[N];   // quantized motion-magnitude depth buffer
__device__ __align__(16) float4 g_acc[N];    // AoS: {weight, c0, c1, c2} per pixel

// One 16-byte vector reduction instead of 4 scalar float atomics.
__device__ __forceinline__ void red_add_v4(float4* p, float a, float b, float c, float d)
{
    asm volatile("red.global.add.v4.f32 [%0], {%1, %2, %3, %4};"
                 :: "l"(p), "f"(a), "f"(b), "f"(c), "f"(d) : "memory");
}

__device__ __forceinline__ int depth_key(float fx, float fy)
{
    // round-half-even (matches jnp.round), IEEE sqrt regardless of fast-math
    return __float2int_rn(__fsqrt_rn(fx * fx + fy * fy) * 1000.0f);
}

// ---------------------------------------------------------------------------
// Pass 1: scatter-max depth buffer + fused g_acc zeroing.
// The zero-stores keep g_acc lines L2-resident for pass 2's RED.ADDs
// (empirically worth ~85us in pass 2 vs zeroing elsewhere).
// All in-bounds corners participate regardless of bilinear weight.
// ---------------------------------------------------------------------------
__global__ void __launch_bounds__(256) k_depth(const float2* __restrict__ flow)
{
    int i = blockIdx.x * blockDim.x + threadIdx.x;
    if (i >= N) return;

    // fused accumulator zeroing (coalesced STG.128)
    g_acc[i] = make_float4(0.f, 0.f, 0.f, 0.f);

    int b = i / HW;
    int p = i - b * HW;
    int h = p / W_;
    int w = p - h * W_;

    float2 f = flow[i];
    int x0 = (int)floorf((float)w + f.x);
    int y0 = (int)floorf((float)h + f.y);
    int d  = depth_key(f.x, f.y);

    int* bufb = g_dbuf + b * HW;
    bool vx0 = (x0 >= 0)     & (x0 < W_);
    bool vx1 = (x0 + 1 >= 0) & (x0 + 1 < W_);
    if (y0 >= 0 && y0 < H_) {
        int* row = bufb + y0 * W_;
        if (vx0) atomicMax(row + x0, d);
        if (vx1) atomicMax(row + x0 + 1, d);
    }
    if (y0 + 1 >= 0 && y0 + 1 < H_) {
        int* row = bufb + (y0 + 1) * W_;
        if (vx0) atomicMax(row + x0, d);
        if (vx1) atomicMax(row + x0 + 1, d);
    }
}

// ---------------------------------------------------------------------------
// Pass 2 helper: depth-test + accumulate both x-corners on one row.
// Gather both corners' depth values with ONE 16B load when they sit inside the
// same 16B-aligned window (x0 % 4 != 3, 75% of cases) -- each scalar gather
// costs a full L1tex wavefront even on hits, so this cuts wavefronts ~40%.
// ---------------------------------------------------------------------------
__device__ __forceinline__ void accum_row(const int* __restrict__ rowd,
                                          float4* __restrict__ rowa,
                                          int x0, int d, float wl, float wr,
                                          float v0, float v1, float v2)
{
    bool vx0 = (x0 >= 0)     & (x0 < W_);
    bool vx1 = (x0 + 1 >= 0) & (x0 + 1 < W_);
    if (!vx0 && !vx1) return;

    int d0 = -1, d1 = -1;
    int r = x0 & 3;
    if (vx0 && vx1 && r != 3) {
        int4 q = __ldg(reinterpret_cast<const int4*>(rowd) + (x0 >> 2));  // 16B aligned
        d0 = (r == 0) ? q.x : (r == 1) ? q.y : q.z;
        d1 = (r == 0) ? q.y : (r == 1) ? q.z : q.w;
    } else {
        if (vx0) d0 = __ldg(rowd + x0);
        if (vx1) d1 = __ldg(rowd + x0 + 1);
    }
    // d >= 0 always, so sentinel -1 never matches
    if (d0 == d && wl != 0.0f) red_add_v4(rowa + x0,     wl, wl * v0, wl * v1, wl * v2);
    if (d1 == d && wr != 0.0f) red_add_v4(rowa + x0 + 1, wr, wr * v0, wr * v1, wr * v2);
}

// ---------------------------------------------------------------------------
// Pass 2: accumulate depth-test winners, ONE vec4 reduction per winning corner.
// ---------------------------------------------------------------------------
__global__ void __launch_bounds__(256) k_accum(const float* __restrict__ im0,
                                               const float2* __restrict__ flow)
{
    int i = blockIdx.x * blockDim.x + threadIdx.x;
    if (i >= N) return;

    int b = i / HW;
    int p = i - b * HW;
    int h = p / W_;
    int w = p - h * W_;

    float2 f = flow[i];
    float x = (float)w + f.x;
    float y = (float)h + f.y;
    float x0f = floorf(x);
    float y0f = floorf(y);
    float ax = x - x0f;
    float ay = y - y0f;
    int x0 = (int)x0f;
    int y0 = (int)y0f;
    int d  = depth_key(f.x, f.y);

    // source pixel values (3 channels, planar, coalesced)
    const float* src = im0 + (size_t)b * 3 * HW + p;
    float v0 = __ldg(src);
    float v1 = __ldg(src + HW);
    float v2 = __ldg(src + 2 * HW);

    float wx1 = ax, wx0 = 1.0f - ax;
    float wy1 = ay, wy0 = 1.0f - ay;

    const int* bufb = g_dbuf + b * HW;
    float4*    accb = g_acc  + b * HW;
    if (y0 >= 0 && y0 < H_)
        accum_row(bufb + y0 * W_, accb + y0 * W_, x0, d,
                  wx0 * wy0, wx1 * wy0, v0, v1, v2);
    if (y0 + 1 >= 0 && y0 + 1 < H_)
        accum_row(bufb + (y0 + 1) * W_, accb + (y0 + 1) * W_, x0, d,
                  wx0 * wy1, wx1 * wy1, v0, v1, v2);
}

// ---------------------------------------------------------------------------
// Pass 3: normalize (4 pixels/thread) + re-zero g_dbuf for the next call.
// out[b][c][h][w] = acc.c / max(acc.w, eps)
// ---------------------------------------------------------------------------
__global__ void __launch_bounds__(256) k_norm(float* __restrict__ out)
{
    int t = blockIdx.x * blockDim.x + threadIdx.x;
    if (t >= N / 4) return;

    int i = t * 4;            // first pixel of this group (HW % 4 == 0 -> same b)
    int b = i / HW;
    int p = i - b * HW;

    float4 a0 = g_acc[i];
    float4 a1 = g_acc[i + 1];
    float4 a2 = g_acc[i + 2];
    float4 a3 = g_acc[i + 3];

    // re-zero depth buffer for the next kernel_launch call (deterministic:
    // loader zeros on first call, this store on all subsequent calls)
    reinterpret_cast<int4*>(g_dbuf)[t] = make_int4(0, 0, 0, 0);

    float r0 = 1.0f / fmaxf(a0.x, 1e-5f);
    float r1 = 1.0f / fmaxf(a1.x, 1e-5f);
    float r2 = 1.0f / fmaxf(a2.x, 1e-5f);
    float r3 = 1.0f / fmaxf(a3.x, 1e-5f);

    float* dst = out + (size_t)b * 3 * HW + p;    // p % 4 == 0 -> 16B aligned
    reinterpret_cast<float4*>(dst)[0]          = make_float4(a0.y * r0, a1.y * r1, a2.y * r2, a3.y * r3);
    reinterpret_cast<float4*>(dst + HW)[0]     = make_float4(a0.z * r0, a1.z * r1, a2.z * r2, a3.z * r3);
    reinterpret_cast<float4*>(dst + 2 * HW)[0] = make_float4(a0.w * r0, a1.w * r1, a2.w * r2, a3.w * r3);
}

// ---------------------------------------------------------------------------
extern "C" void kernel_launch(void* const* d_in, const int* in_sizes, int n_in,
                              void* d_out, int out_size)
{
    const float*  im0  = (const float*)d_in[0];   // [B,C,H,W] float32
    const float2* flow = (const float2*)d_in[1];  // [B,H,W,2] float32
    float*        out  = (float*)d_out;           // [B,C,H,W] float32

    const int T = 256;
    k_depth<<<(N + T - 1) / T, T>>>(flow);
    k_accum<<<(N + T - 1) / T, T>>>(im0, flow);
    k_norm <<<(N / 4 + T - 1) / T, T>>>(out);

    (void)in_sizes; (void)n_in; (void)out_size;
}